// round 5
// baseline (speedup 1.0000x reference)
#include <cuda_runtime.h>
#include <cuda_fp16.h>
#include <mma.h>
#include <cstdint>

using namespace nvcuda;

// ---------------- problem constants -----------------------------------------
#define RB   64
#define RT   512
#define RDI  512
#define RH   1024
#define RDO  512
#define BH   (RB * RH)

// ---------------- rec tiling --------------------------------------------------
#define KC    256                    // k-chunk (halves)
#define LDHs  264                    // KC + 8
#define LDWs  1032                   // RH + 8
#define L0_CTAS 32
#define L1_CTAS 64
#define NBUF  4                      // staging ring depth
#define REC_SMEM_BYTES 218112

// ---------------- GEMM tiling (pre0 only) -------------------------------------
#define GBM 128
#define GBN 128
#define GBK 32
#define GLD 36
#define GEMM_SMEM_BYTES (2 * (GBM * GLD + GBN * GLD) * 4)

// ---------------- scratch ------------------------------------------------------
__device__ float    g_pre[RT * BH];      // fp32 pre-activations (layer 0)
__device__ __half   g_h1h[RT * BH];      // layer-0 hidden history (fp16)
__device__ __half   g_h2h[RT * BH];      // layer-1 hidden history (fp16)
__device__ unsigned g_cnt[64];           // [0]=L0 counter, [32]=L1 counter (sep lines)

// ---------------- helpers ------------------------------------------------------
__device__ __forceinline__ float to_tf32(float x) {
    float r;
    asm("cvt.rna.tf32.f32 %0, %1;" : "=f"(r) : "f"(x));
    return r;
}
__device__ __forceinline__ unsigned ld_rlx(const unsigned* p) {
    unsigned v;
    asm volatile("ld.relaxed.gpu.u32 %0, [%1];" : "=r"(v) : "l"(p) : "memory");
    return v;
}
__device__ __forceinline__ void red_release(unsigned* p) {
    asm volatile("red.release.gpu.global.add.u32 [%0], %1;" :: "l"(p), "r"(1u) : "memory");
}
__device__ __forceinline__ void cpa16(uint32_t dst, const void* src) {
    asm volatile("cp.async.cg.shared.global [%0], [%1], 16;" :: "r"(dst), "l"(src));
}
#define CP_COMMIT() asm volatile("cp.async.commit_group;" ::: "memory")
#define CP_WAIT0()  asm volatile("cp.async.wait_group 0;"  ::: "memory")
#define CP_WAIT1()  asm volatile("cp.async.wait_group 1;"  ::: "memory")
#define CP_WAIT2()  asm volatile("cp.async.wait_group 2;"  ::: "memory")

// ---------------- TF32 GEMM for pre0 -------------------------------------------
__global__ __launch_bounds__(256)
void gemm_tf32(const float* __restrict__ A, const float* __restrict__ W,
               float* __restrict__ out, int K, int sA_t, int sA_b)
{
    extern __shared__ float sm[];
    float* As = sm;
    float* Bs = sm + 2 * GBM * GLD;

    const int tid = threadIdx.x;
    const int wid = tid >> 5;
    const int wm  = wid & 1;
    const int wn  = wid >> 1;
    const int bx  = blockIdx.x;
    const int by  = blockIdx.y;

    const int lRow = tid >> 1;
    const int lC   = (tid & 1) * 16;
    const int r    = by * GBM + lRow;
    const int tt   = r >> 6;
    const int bb   = r & 63;
    const float* aPtr = A + (size_t)bb * sA_b + (size_t)tt * sA_t + lC;
    const float* wPtr = W + (size_t)(bx * GBN + lRow) * K + lC;

    wmma::fragment<wmma::accumulator, 16, 16, 8, float> acc[4][2];
    #pragma unroll
    for (int i = 0; i < 4; i++)
        #pragma unroll
        for (int j = 0; j < 2; j++) wmma::fill_fragment(acc[i][j], 0.0f);

    float4 ra[4], rb[4];
    #pragma unroll
    for (int p = 0; p < 4; p++) {
        ra[p] = *(const float4*)(aPtr + p * 4);
        rb[p] = *(const float4*)(wPtr + p * 4);
    }

    const int niter = K / GBK;
    for (int c = 0; c < niter; c++) {
        {
            float* dA = As + (c & 1) * GBM * GLD + lRow * GLD + lC;
            float* dB = Bs + (c & 1) * GBN * GLD + lRow * GLD + lC;
            #pragma unroll
            for (int p = 0; p < 4; p++) {
                dA[p*4+0] = to_tf32(ra[p].x); dA[p*4+1] = to_tf32(ra[p].y);
                dA[p*4+2] = to_tf32(ra[p].z); dA[p*4+3] = to_tf32(ra[p].w);
                dB[p*4+0] = to_tf32(rb[p].x); dB[p*4+1] = to_tf32(rb[p].y);
                dB[p*4+2] = to_tf32(rb[p].z); dB[p*4+3] = to_tf32(rb[p].w);
            }
        }
        if (c + 1 < niter) {
            const float* a2 = aPtr + (c + 1) * GBK;
            const float* w2 = wPtr + (c + 1) * GBK;
            #pragma unroll
            for (int p = 0; p < 4; p++) {
                ra[p] = *(const float4*)(a2 + p * 4);
                rb[p] = *(const float4*)(w2 + p * 4);
            }
        }
        __syncthreads();

        const float* bufA = As + (c & 1) * GBM * GLD;
        const float* bufB = Bs + (c & 1) * GBN * GLD;
        #pragma unroll
        for (int s = 0; s < 4; s++) {
            wmma::fragment<wmma::matrix_a, 16, 16, 8, wmma::precision::tf32, wmma::row_major> af[4];
            wmma::fragment<wmma::matrix_b, 16, 16, 8, wmma::precision::tf32, wmma::col_major> bf[2];
            #pragma unroll
            for (int i = 0; i < 4; i++)
                wmma::load_matrix_sync(af[i], bufA + (wm * 64 + i * 16) * GLD + s * 8, GLD);
            #pragma unroll
            for (int j = 0; j < 2; j++)
                wmma::load_matrix_sync(bf[j], bufB + (wn * 32 + j * 16) * GLD + s * 8, GLD);
            #pragma unroll
            for (int i = 0; i < 4; i++)
                #pragma unroll
                for (int j = 0; j < 2; j++)
                    wmma::mma_sync(acc[i][j], af[i], bf[j], acc[i][j]);
        }
        __syncthreads();
    }

    #pragma unroll
    for (int i = 0; i < 4; i++)
        #pragma unroll
        for (int j = 0; j < 2; j++) {
            const int rr = by * GBM + wm * 64 + i * 16;
            const int cc = bx * GBN + wn * 32 + j * 16;
            wmma::store_matrix_sync(out + (size_t)rr * RH + cc, acc[i][j], RH, wmma::mem_row_major);
        }
}

// ---------------- fused wavefront recurrence -----------------------------------
// NC = columns per CTA, NMAT = 1 (L0: hh only, pre from gmem) or 2 (L1: ih+hh).
// Depth-4 cp.async staging ring, 1 bar per chunk, split producer waits.
template<int NC, int NMAT>
__device__ __forceinline__ void rec_role(
    int cta, char* smraw,
    const float* __restrict__ pre,
    const float* __restrict__ WA, const float* __restrict__ WB,
    const float* __restrict__ bi, const float* __restrict__ bh,
    const __half* __restrict__ srcA, const __half* __restrict__ srcB,
    __half* __restrict__ dst,
    const unsigned* cntA, unsigned mulA, int aheadA, int lagA,
    const unsigned* cntB, unsigned mulB,
    unsigned* myCnt)
{
    __half* Ws  = (__half*)smraw;                  // NMAT*NC*LDWs halves
    __half* stg = Ws + NMAT * NC * LDWs;           // NBUF * RB * LDHs halves
    float*  rs  = (float*)(stg + NBUF * RB * LDHs);// 2*4*(NC/16)*256 floats
    float*  sb  = rs + 2 * 4 * (NC / 16) * 256;    // NC floats

    const int tid   = threadIdx.x;
    const int wid   = tid >> 5;
    const int mt    = wid >> 1;
    const int ks    = wid & 1;
    const int ncol0 = cta * NC;

    // resident W slices as fp16
    #pragma unroll 1
    for (int m = 0; m < NMAT; m++) {
        const float* W = m ? WB : WA;
        for (int i = tid; i < NC * RH / 8; i += 256) {
            const int n  = i / (RH / 8);
            const int k8 = i % (RH / 8);
            const float* wp = W + (size_t)(ncol0 + n) * RH + k8 * 8;
            float4 v0 = *(const float4*)(wp);
            float4 v1 = *(const float4*)(wp + 4);
            __half2* d = (__half2*)(Ws + m * NC * LDWs + n * LDWs + k8 * 8);
            d[0] = __floats2half2_rn(v0.x, v0.y);
            d[1] = __floats2half2_rn(v0.z, v0.w);
            d[2] = __floats2half2_rn(v1.x, v1.y);
            d[3] = __floats2half2_rn(v1.z, v1.w);
        }
    }
    if (tid < NC) sb[tid] = bi[ncol0 + tid] + bh[ncol0 + tid];
    __syncthreads();

    const uint32_t stg_u32 = (uint32_t)__cvta_generic_to_shared(stg);
    const int srow = tid >> 2;
    const int scol = (tid & 3) * 64;

    const int eb   = tid >> 2;
    const int embt = eb >> 4;
    const int ebr  = eb & 15;
    const int en0  = (tid & 3) * (NC / 4);

    #pragma unroll 1
    for (int t = 0; t < RT; ++t) {
        // prefetch pre[t] into regs (L0 only; independent of all waits)
        float pv[NC / 4];
        if (NMAT == 1) {
            const float* prow = pre + (size_t)t * BH + eb * RH + ncol0 + en0;
            #pragma unroll
            for (int j = 0; j < NC / 4; j += 4) {
                float4 v = *(const float4*)(prow + j);
                pv[j] = v.x; pv[j+1] = v.y; pv[j+2] = v.z; pv[j+3] = v.w;
            }
        }

        // ---- wait on srcA producers ----
        if (tid == 0 && (t + aheadA > 0)) {
            const unsigned tgt = mulA * (unsigned)(t + aheadA);
            while (ld_rlx(cntA) < tgt) { }
            asm volatile("fence.acq_rel.gpu;" ::: "memory");
        }
        __syncthreads();

        const int nchk = (NMAT == 2) ? (t > 0 ? 8 : 4) : (t > 0 ? 4 : 0);

        // chunk staging issue: ic<4 -> srcA (ih / own-prev for L0), ic>=4 -> srcB
        auto issue = [&](int ic) {
            const __half* base;
            int kcol;
            if (NMAT == 2 && ic >= 4) {
                base = srcB + (size_t)(t - 1) * BH;  kcol = (ic - 4) * KC;
            } else {
                base = srcA + (size_t)(t - lagA) * BH;  kcol = ic * KC;
            }
            const __half* s = base + srow * RH + kcol + scol;
            const uint32_t d = stg_u32 + (((ic & (NBUF - 1)) * RB * LDHs)
                                          + srow * LDHs + scol) * 2;
            #pragma unroll
            for (int j = 0; j < 8; j++) cpa16(d + j * 16, s + j * 8);
            CP_COMMIT();
        };

        // prologue: fill the ring (chunks 0..2 are always srcA side)
        const int npro = nchk < 3 ? nchk : 3;
        for (int ic = 0; ic < npro; ic++) issue(ic);

        wmma::fragment<wmma::accumulator, 16, 16, 16, float> acc[NC / 16];
        #pragma unroll
        for (int i = 0; i < NC / 16; i++) wmma::fill_fragment(acc[i], 0.0f);

        #pragma unroll 1
        for (int c = 0; c < nchk; c++) {
            // wait for chunk c (per-thread groups), then make visible CTA-wide
            if (c <= nchk - 3)      { CP_WAIT2(); }
            else if (c == nchk - 2) { CP_WAIT1(); }
            else                    { CP_WAIT0(); }
            __syncthreads();

            // issue chunk c+3 (buffer (c-1)&3 is free: all warps passed the bar)
            if (c + 3 < nchk) {
                const int ic = c + 3;
                if (NMAT == 2 && ic == 4) {
                    // first own-dep chunk: wait for h2[t-1] now (overlapped w/ ih work)
                    if (tid == 0) {
                        const unsigned tgt = mulB * (unsigned)t;
                        while (ld_rlx(cntB) < tgt) { }
                        asm volatile("fence.acq_rel.gpu;" ::: "memory");
                    }
                    __syncthreads();
                }
                issue(ic);
            }

            const __half* buf = stg + (c & (NBUF - 1)) * RB * LDHs;
            const __half* Wb  = Ws + ((NMAT == 2 && c >= 4) ? 1 : 0) * NC * LDWs
                                   + (c & 3) * KC;
            #pragma unroll
            for (int s8 = 0; s8 < 8; s8++) {
                const int k = ks * 128 + s8 * 16;
                wmma::fragment<wmma::matrix_a, 16, 16, 16, __half, wmma::row_major> af;
                wmma::load_matrix_sync(af, buf + (mt * 16) * LDHs + k, LDHs);
                #pragma unroll
                for (int nt = 0; nt < NC / 16; nt++) {
                    wmma::fragment<wmma::matrix_b, 16, 16, 16, __half, wmma::col_major> bf;
                    wmma::load_matrix_sync(bf, Wb + (nt * 16) * LDWs + k, LDWs);
                    wmma::mma_sync(acc[nt], af, bf, acc[nt]);
                }
            }
        }

        // ---- k-split reduce + tanh + publish ----
        float a[NC / 4];
        #pragma unroll
        for (int j = 0; j < NC / 4; j++) a[j] = 0.f;
        if (nchk > 0) {
            #pragma unroll
            for (int nt = 0; nt < NC / 16; nt++)
                wmma::store_matrix_sync(rs + ((ks * 4 + mt) * (NC / 16) + nt) * 256,
                                        acc[nt], 16, wmma::mem_row_major);
            __syncthreads();
            #pragma unroll
            for (int j = 0; j < NC / 4; j++) {
                const int nl = en0 + j;
                const int nt = nl >> 4;
                const int nc = nl & 15;
                a[j] = rs[((0 * 4 + embt) * (NC / 16) + nt) * 256 + ebr * 16 + nc]
                     + rs[((1 * 4 + embt) * (NC / 16) + nt) * 256 + ebr * 16 + nc];
            }
        }
        {
            __half* drow = dst + (size_t)t * BH + eb * RH + ncol0 + en0;
            #pragma unroll
            for (int j = 0; j < NC / 4; j += 2) {
                float s0 = a[j]     + sb[en0 + j];
                float s1 = a[j + 1] + sb[en0 + j + 1];
                if (NMAT == 1) { s0 += pv[j]; s1 += pv[j + 1]; }
                *(__half2*)(drow + j) = __floats2half2_rn(tanhf(s0), tanhf(s1));
            }
        }
        __syncthreads();
        if (tid == 0) red_release(myCnt);
    }
}

__global__ __launch_bounds__(256)
void rec_fused(const float* __restrict__ pre0,
               const float* __restrict__ Whh0,
               const float* __restrict__ bih0, const float* __restrict__ bhh0,
               const float* __restrict__ Wih1, const float* __restrict__ Whh1,
               const float* __restrict__ bih1, const float* __restrict__ bhh1)
{
    extern __shared__ char smraw[];
    if (blockIdx.x < L0_CTAS) {
        rec_role<32, 1>(blockIdx.x, smraw, pre0, Whh0, nullptr, bih0, bhh0,
                        g_h1h, nullptr, g_h1h,
                        &g_cnt[0], L0_CTAS, 0, 1,
                        nullptr, 0, &g_cnt[0]);
    } else {
        rec_role<16, 2>(blockIdx.x - L0_CTAS, smraw, nullptr, Wih1, Whh1, bih1, bhh1,
                        g_h1h, g_h2h, g_h2h,
                        &g_cnt[0], L0_CTAS, 1, 0,
                        &g_cnt[32], L1_CTAS, &g_cnt[32]);
    }
}

// ---------------- FC head ------------------------------------------------------
__global__ __launch_bounds__(256)
void fc_kernel(const __half* __restrict__ h, const float* __restrict__ Wfc,
               const float* __restrict__ bfc, float* __restrict__ out)
{
    const int w    = (blockIdx.x * blockDim.x + threadIdx.x) >> 5;
    const int lane = threadIdx.x & 31;
    if (w >= RB * RDO) return;
    const int b = w >> 9;
    const int o = w & (RDO - 1);

    const __half* hp = h   + (size_t)b * RH;
    const float*  wp = Wfc + (size_t)o * RH;
    float acc = 0.f;
    #pragma unroll
    for (int k = lane * 8; k < RH; k += 256) {
        const __half2* hv = (const __half2*)(hp + k);
        #pragma unroll
        for (int q = 0; q < 4; q++) {
            float2 hf = __half22float2(hv[q]);
            acc += hf.x * wp[k + q * 2] + hf.y * wp[k + q * 2 + 1];
        }
    }
    #pragma unroll
    for (int s = 16; s > 0; s >>= 1) acc += __shfl_xor_sync(0xffffffffu, acc, s);
    if (lane == 0) out[w] = acc + bfc[o];
}

// ---------------- launch -------------------------------------------------------
extern "C" void kernel_launch(void* const* d_in, const int* in_sizes, int n_in,
                              void* d_out, int out_size)
{
    const float* x     = (const float*)d_in[0];
    const float* W_ih0 = (const float*)d_in[1];
    const float* W_hh0 = (const float*)d_in[2];
    const float* b_ih0 = (const float*)d_in[3];
    const float* b_hh0 = (const float*)d_in[4];
    const float* W_ih1 = (const float*)d_in[5];
    const float* W_hh1 = (const float*)d_in[6];
    const float* b_ih1 = (const float*)d_in[7];
    const float* b_hh1 = (const float*)d_in[8];
    const float* W_fc  = (const float*)d_in[9];
    const float* b_fc  = (const float*)d_in[10];

    float*  pre;
    __half* h2;
    unsigned* cnt;
    cudaGetSymbolAddress((void**)&pre, g_pre);
    cudaGetSymbolAddress((void**)&h2,  g_h2h);
    cudaGetSymbolAddress((void**)&cnt, g_cnt);

    cudaFuncSetAttribute(gemm_tf32, cudaFuncAttributeMaxDynamicSharedMemorySize, GEMM_SMEM_BYTES);
    cudaFuncSetAttribute(rec_fused, cudaFuncAttributeMaxDynamicSharedMemorySize, REC_SMEM_BYTES);

    cudaMemsetAsync(cnt, 0, 64 * sizeof(unsigned), 0);

    dim3 ggrid(RH / GBN, (RT * RB) / GBM);
    gemm_tf32<<<ggrid, 256, GEMM_SMEM_BYTES>>>(x, W_ih0, pre, RDI, RDI, RT * RDI);

    rec_fused<<<L0_CTAS + L1_CTAS, 256, REC_SMEM_BYTES>>>(
        pre, W_hh0, b_ih0, b_hh0, W_ih1, W_hh1, b_ih1, b_hh1);

    fc_kernel<<<(RB * RDO) / 8, 256>>>(h2 + (size_t)(RT - 1) * BH,
                                       W_fc, b_fc, (float*)d_out);
}